// round 12
// baseline (speedup 1.0000x reference)
#include <cuda_runtime.h>
#include <cuda_bf16.h>
#include <cstdint>

#define NODES 40000
#define EDGES 640000
#define DIN   128
#define HC    128
#define OC    64
#define NTILES 5000   // 128 edges per tile

typedef unsigned long long ull;

// single dynamic-shared declaration for the whole TU
extern __shared__ char dynsm[];

// ---------------- device scratch ------------------------------------------
__device__ float g_xm[(size_t)NODES * HC];
__device__ float g_xs[(size_t)NODES * OC];
__device__ float g_denom[(size_t)NODES * 2];
__device__ float g_agg[(size_t)NODES * HC];
__device__ float g_le_fallback[(size_t)EDGES * HC];
// W_edge^T split into bf16 hi/lo: [n][k-pair] padded row stride 68 words
__device__ __align__(16) uint32_t g_Bhi[128 * 68];
__device__ __align__(16) uint32_t g_Blo[128 * 68];

// ---------------- helpers ----------------------------------------------------
__device__ __forceinline__ void red_add_v2(float* p, float a, float b) {
    asm volatile("red.global.add.v2.f32 [%0], {%1,%2};"
                 :: "l"(p), "f"(a), "f"(b) : "memory");
}
__device__ __forceinline__ void red_add_f32(float* p, float v) {
    asm volatile("red.global.add.f32 [%0], %1;" :: "l"(p), "f"(v) : "memory");
}
// m16n8k16 row.col bf16 MMA, f32 accumulate (base-target HMMA)
__device__ __forceinline__ void mma_bf16(float* c, const uint32_t* a, const uint32_t* b) {
    asm volatile("mma.sync.aligned.m16n8k16.row.col.f32.bf16.bf16.f32 "
                 "{%0,%1,%2,%3}, {%4,%5,%6,%7}, {%8,%9}, {%0,%1,%2,%3};"
                 : "+f"(c[0]), "+f"(c[1]), "+f"(c[2]), "+f"(c[3])
                 : "r"(a[0]), "r"(a[1]), "r"(a[2]), "r"(a[3]), "r"(b[0]), "r"(b[1]));
}
__device__ __forceinline__ uint32_t pack_bf16x2_split(float v0, float v1, uint32_t& lo) {
    __nv_bfloat16 h0 = __float2bfloat16_rn(v0);
    __nv_bfloat16 h1 = __float2bfloat16_rn(v1);
    __nv_bfloat16 l0 = __float2bfloat16_rn(v0 - __bfloat162float(h0));
    __nv_bfloat16 l1 = __float2bfloat16_rn(v1 - __bfloat162float(h1));
    lo = (uint32_t)__bfloat16_as_ushort(l0) | ((uint32_t)__bfloat16_as_ushort(l1) << 16);
    return (uint32_t)__bfloat16_as_ushort(h0) | ((uint32_t)__bfloat16_as_ushort(h1) << 16);
}

// ---------------- K0: init --------------------------------------------------
__global__ void init_kernel() {
    int i = blockIdx.x * blockDim.x + threadIdx.x;
    if (i < NODES * HC) g_agg[i] = 0.0f;
    if (i < NODES * 2)  g_denom[i] = 0.0f;
}

// ---------------- prep: W_edge^T -> bf16 hi/lo padded [n][k] images ----------
__global__ void prep_kernel(const float* __restrict__ W_edge) {
    int p = blockIdx.x * 256 + threadIdx.x;   // 8192 = 128 n x 64 k-pairs
    if (p >= 8192) return;
    int n  = p >> 6;
    int kp = p & 63;
    int k  = kp * 2;
    uint32_t lo;
    uint32_t hi = pack_bf16x2_split(W_edge[k * HC + n], W_edge[(k + 1) * HC + n], lo);
    g_Bhi[n * 68 + kp] = hi;
    g_Blo[n * 68 + kp] = lo;
}

// ---------------- K1: node GEMMs (known-good) --------------------------------
__global__ void node_kernel(const float* __restrict__ x,
                            const float* __restrict__ W_msg,
                            const float* __restrict__ b_msg,
                            const float* __restrict__ W_self,
                            const float* __restrict__ b_self) {
    float* smf = (float*)dynsm;
    float* Xs = smf;
    float* Wm = smf + 64 * 128;
    float* Wf = Wm + 128 * 128;
    int tid = threadIdx.x;

    const float4* xg = (const float4*)(x + (size_t)blockIdx.x * 64 * DIN);
#pragma unroll
    for (int i = 0; i < 8; i++)  ((float4*)Xs)[tid + i * 256] = xg[tid + i * 256];
#pragma unroll
    for (int i = 0; i < 16; i++) ((float4*)Wm)[tid + i * 256] = ((const float4*)W_msg)[tid + i * 256];
#pragma unroll
    for (int i = 0; i < 8; i++)  ((float4*)Wf)[tid + i * 256] = ((const float4*)W_self)[tid + i * 256];
    __syncthreads();

    int lane = tid & 31, ty = tid >> 5;
    int lane4 = lane * 4;
    const float* Xr = Xs + ty * 8 * DIN;
    {
        float acc[8][4];
#pragma unroll
        for (int r = 0; r < 8; r++) { acc[r][0] = acc[r][1] = acc[r][2] = acc[r][3] = 0.f; }
#pragma unroll 4
        for (int k = 0; k < 128; k++) {
            float4 bq = *(float4*)(Wm + k * 128 + lane4);
#pragma unroll
            for (int r = 0; r < 8; r++) {
                float av = Xr[r * DIN + k];
                acc[r][0] += av * bq.x; acc[r][1] += av * bq.y;
                acc[r][2] += av * bq.z; acc[r][3] += av * bq.w;
            }
        }
        float4 bm = *(const float4*)(b_msg + lane4);
#pragma unroll
        for (int r = 0; r < 8; r++) {
            int n = blockIdx.x * 64 + ty * 8 + r;
            float4 v; v.x = acc[r][0] + bm.x; v.y = acc[r][1] + bm.y;
            v.z = acc[r][2] + bm.z; v.w = acc[r][3] + bm.w;
            *(float4*)(g_xm + (size_t)n * HC + lane4) = v;
        }
    }
    {
        int lane2 = lane * 2;
        float acc[8][2];
#pragma unroll
        for (int r = 0; r < 8; r++) { acc[r][0] = acc[r][1] = 0.f; }
#pragma unroll 4
        for (int k = 0; k < 128; k++) {
            float2 bq = *(float2*)(Wf + k * 64 + lane2);
#pragma unroll
            for (int r = 0; r < 8; r++) {
                float av = Xr[r * DIN + k];
                acc[r][0] += av * bq.x; acc[r][1] += av * bq.y;
            }
        }
        float2 bs = *(const float2*)(b_self + lane2);
#pragma unroll
        for (int r = 0; r < 8; r++) {
            int n = blockIdx.x * 64 + ty * 8 + r;
            float2 v; v.x = acc[r][0] + bs.x; v.y = acc[r][1] + bs.y;
            *(float2*)(g_xs + (size_t)n * OC + lane2) = v;
        }
    }
}

// ---------------- K2: warp-autonomous HMMA edge GEMM + fused scatter ---------
// R10 structure (best) + cross-tile software pipelining:
//   - at ks==7 the raw A regs are dead -> load NEXT tile's first chunk there
//     (DRAM latency drains behind the epilogue, zero extra registers)
//   - src/dst indices for the epilogue loaded at tile start (drain behind MMA)
// Persistent CTAs, 2/SM. Tile = 128 edges; warp = 32 rows x 64 cols as two
// stacked m16 tiles sharing B fragments. No __syncthreads in the tile loop.
// warp w: rows [(w>>1)*32,+32), cols [(w&1)*64,+64)  (col half == head)
// smem: 0: bias[128] | 512: att[128] | 1024: B_hi(34816) | 35840: B_lo(34816)
#define SM_BHI   1024
#define SM_BLO   35840
#define SM_TOTAL 70656

__global__ void __launch_bounds__(256, 2) edge_kernel(
        const float* __restrict__ edge_attr,
        const float* __restrict__ b_edge,
        const float* __restrict__ att,
        const int*   __restrict__ srcIdx,
        const int*   __restrict__ dstIdx,
        float* __restrict__ le_out) {
    char* sm = dynsm;
    int tid = threadIdx.x;
    int wid = tid >> 5;
    int lane = tid & 31;
    float* b_s   = (float*)(sm);
    float* att_s = (float*)(sm + 512);
    uint32_t* Bh32 = (uint32_t*)(sm + SM_BHI);
    uint32_t* Bl32 = (uint32_t*)(sm + SM_BLO);

    // ---- prologue (once per CTA) ----
    if (tid < 128) { b_s[tid] = b_edge[tid]; att_s[tid] = att[tid]; }
    {
        const uint4* bh = (const uint4*)g_Bhi;
        const uint4* bl = (const uint4*)g_Blo;
        uint4* dh = (uint4*)Bh32;
        uint4* dl = (uint4*)Bl32;
#pragma unroll
        for (int i = 0; i < 9; i++) {
            int idx = tid + i * 256;
            if (idx < 2176) { dh[idx] = bh[idx]; dl[idx] = bl[idx]; }
        }
    }
    __syncthreads();   // the only block sync

    int rowg = wid >> 1;          // 0..3 -> rows rowg*32..+32
    int colg = wid & 1;           // 0..1 -> cols colg*64..+64  (== head)
    int r   = lane >> 2;          // 0..7
    int tig = lane & 3;           // 0..3
    int r0  = rowg * 32 + r;      // lane covers rows r0, r0+8 (mt=0), r0+16, r0+24 (mt=1)

    // initial A chunk for the first tile (ks=0)
    float2 raw[2][4];
    {
        int t0 = blockIdx.x;
        const float2* A = (const float2*)(edge_attr + (size_t)t0 * 128 * DIN);
        int kw = tig;
#pragma unroll
        for (int mt = 0; mt < 2; mt++) {
            int R = r0 + mt * 16;
            raw[mt][0] = A[R * 64 + kw];       raw[mt][1] = A[(R + 8) * 64 + kw];
            raw[mt][2] = A[R * 64 + kw + 4];   raw[mt][3] = A[(R + 8) * 64 + kw + 4];
        }
    }

    for (int t = blockIdx.x; t < NTILES; t += gridDim.x) {
        const float2* A = (const float2*)(edge_attr + (size_t)t * 128 * DIN);
        int tn = t + gridDim.x;
        // next tile base for the ks==7 cross-tile prefetch (clamped: harmless reload)
        const float2* An = (const float2*)(edge_attr +
                            (size_t)(tn < NTILES ? tn : t) * 128 * DIN);

        // epilogue indices prefetched now; latency drains behind the MMA loop
        int eb = t * 128 + r0;
        int s00 = srcIdx[eb],      s01 = srcIdx[eb + 8];
        int s10 = srcIdx[eb + 16], s11 = srcIdx[eb + 24];
        int d00 = dstIdx[eb],      d01 = dstIdx[eb + 8];
        int d10 = dstIdx[eb + 16], d11 = dstIdx[eb + 24];

        float acc[2][8][4];
#pragma unroll
        for (int mt = 0; mt < 2; mt++)
#pragma unroll
            for (int nf = 0; nf < 8; nf++)
#pragma unroll
                for (int q = 0; q < 4; q++) acc[mt][nf][q] = 0.f;

#pragma unroll
        for (int ks = 0; ks < 8; ks++) {
            int kw = ks * 8 + tig;
            uint32_t ah[2][4], al[2][4];
#pragma unroll
            for (int mt = 0; mt < 2; mt++) {
                ah[mt][0] = pack_bf16x2_split(raw[mt][0].x, raw[mt][0].y, al[mt][0]);
                ah[mt][1] = pack_bf16x2_split(raw[mt][1].x, raw[mt][1].y, al[mt][1]);
                ah[mt][2] = pack_bf16x2_split(raw[mt][2].x, raw[mt][2].y, al[mt][2]);
                ah[mt][3] = pack_bf16x2_split(raw[mt][3].x, raw[mt][3].y, al[mt][3]);
            }
            {
                // ks<7: next chunk of this tile; ks==7: FIRST chunk of next tile
                const float2* Asrc = (ks < 7) ? A : An;
                int kn = (ks < 7) ? (kw + 8) : tig;
#pragma unroll
                for (int mt = 0; mt < 2; mt++) {
                    int R = r0 + mt * 16;
                    raw[mt][0] = Asrc[R * 64 + kn];       raw[mt][1] = Asrc[(R + 8) * 64 + kn];
                    raw[mt][2] = Asrc[R * 64 + kn + 4];   raw[mt][3] = Asrc[(R + 8) * 64 + kn + 4];
                }
            }
#pragma unroll
            for (int nf = 0; nf < 8; nf++) {
                int nb = (colg * 64 + nf * 8 + r) * 68 + kw;
                uint32_t bh[2] = { Bh32[nb], Bh32[nb + 4] };
                uint32_t bl[2] = { Bl32[nb], Bl32[nb + 4] };
#pragma unroll
                for (int mt = 0; mt < 2; mt++) {
                    mma_bf16(acc[mt][nf], ah[mt], bh);
                    mma_bf16(acc[mt][nf], ah[mt], bl);
                    mma_bf16(acc[mt][nf], al[mt], bh);
                }
            }
        }

        // ---- epilogue straight from fragments (per m-tile) ----
#pragma unroll
        for (int mt = 0; mt < 2; mt++) {
            int e0 = t * 128 + r0 + mt * 16;
            int e1 = e0 + 8;
            int s0 = mt ? s10 : s00, s1 = mt ? s11 : s01;
            int d0 = mt ? d10 : d00, d1 = mt ? d11 : d01;

            float dot0 = 0.f, dot1 = 0.f;
#pragma unroll
            for (int nf = 0; nf < 8; nf++) {
                int col = colg * 64 + nf * 8 + tig * 2;
                float2 bb = *(float2*)(b_s + col);
                float2 le0; le0.x = acc[mt][nf][0] + bb.x; le0.y = acc[mt][nf][1] + bb.y;
                float2 le1; le1.x = acc[mt][nf][2] + bb.x; le1.y = acc[mt][nf][3] + bb.y;
                *(float2*)(le_out + (size_t)e0 * HC + col) = le0;
                *(float2*)(le_out + (size_t)e1 * HC + col) = le1;
                float2 xv0 = *(const float2*)(g_xm + (size_t)s0 * HC + col);
                float2 xv1 = *(const float2*)(g_xm + (size_t)s1 * HC + col);
                acc[mt][nf][0] = le0.x + xv0.x; acc[mt][nf][1] = le0.y + xv0.y;
                acc[mt][nf][2] = le1.x + xv1.x; acc[mt][nf][3] = le1.y + xv1.y;
                float2 at = *(float2*)(att_s + col);
                dot0 += acc[mt][nf][0] * at.x + acc[mt][nf][1] * at.y;
                dot1 += acc[mt][nf][2] * at.x + acc[mt][nf][3] * at.y;
            }
            dot0 += __shfl_xor_sync(0xffffffffu, dot0, 1);
            dot0 += __shfl_xor_sync(0xffffffffu, dot0, 2);
            dot1 += __shfl_xor_sync(0xffffffffu, dot1, 1);
            dot1 += __shfl_xor_sync(0xffffffffu, dot1, 2);
            float lr0 = dot0 > 0.f ? dot0 : 0.2f * dot0;
            float lr1 = dot1 > 0.f ? dot1 : 0.2f * dot1;
            float ex0 = __expf(lr0);
            float ex1 = __expf(lr1);
            if (tig == 0) {
                red_add_f32(&g_denom[d0 * 2 + colg], ex0);
                red_add_f32(&g_denom[d1 * 2 + colg], ex1);
            }
#pragma unroll
            for (int nf = 0; nf < 8; nf++) {
                int col = colg * 64 + nf * 8 + tig * 2;
                red_add_v2(g_agg + (size_t)d0 * HC + col, acc[mt][nf][0] * ex0, acc[mt][nf][1] * ex0);
                red_add_v2(g_agg + (size_t)d1 * HC + col, acc[mt][nf][2] * ex1, acc[mt][nf][3] * ex1);
            }
        }
    }
}

// ---------------- K3: finalize ----------------------------------------------
__global__ void finalize_kernel(float* __restrict__ out) {
    int i = blockIdx.x * blockDim.x + threadIdx.x;
    if (i >= NODES * OC) return;
    int n = i >> 6;
    int c = i & 63;
    float d0 = g_denom[n * 2 + 0] + 1e-16f;
    float d1 = g_denom[n * 2 + 1] + 1e-16f;
    float v = 0.5f * (g_agg[(size_t)n * HC + c] / d0 + g_agg[(size_t)n * HC + 64 + c] / d1);
    out[i] = v + g_xs[i];
}

// ---------------- launch ------------------------------------------------------
extern "C" void kernel_launch(void* const* d_in, const int* in_sizes, int n_in,
                              void* d_out, int out_size) {
    const float* x        = (const float*)d_in[0];
    const float* edge_attr= (const float*)d_in[1];
    const float* W_msg    = (const float*)d_in[2];
    const float* b_msg    = (const float*)d_in[3];
    const float* W_edge   = (const float*)d_in[4];
    const float* b_edge   = (const float*)d_in[5];
    const float* W_self   = (const float*)d_in[6];
    const float* b_self   = (const float*)d_in[7];
    const float* att      = (const float*)d_in[8];
    const int*   ei       = (const int*)d_in[9];
    const int* srcI = ei;
    const int* dstI = ei + EDGES;

    float* out = (float*)d_out;
    float* le_out;
    bool le_in_out = (out_size >= NODES * OC + (long long)EDGES * HC);
    if (le_in_out) {
        le_out = out + (size_t)NODES * OC;
    } else {
        void* p = nullptr;
        cudaGetSymbolAddress(&p, g_le_fallback);
        le_out = (float*)p;
    }

    cudaFuncSetAttribute(node_kernel, cudaFuncAttributeMaxDynamicSharedMemorySize, 131072);
    cudaFuncSetAttribute(edge_kernel, cudaFuncAttributeMaxDynamicSharedMemorySize, SM_TOTAL);

    init_kernel<<<(NODES * HC + 255) / 256, 256>>>();
    prep_kernel<<<32, 256>>>(W_edge);
    node_kernel<<<NODES / 64, 256, 131072>>>(x, W_msg, b_msg, W_self, b_self);
    edge_kernel<<<296, 256, SM_TOTAL>>>(edge_attr, b_edge, att, srcI, dstI, le_out);
    finalize_kernel<<<(NODES * OC + 255) / 256, 256>>>(out);
}

// round 13
// speedup vs baseline: 1.0541x; 1.0541x over previous
#include <cuda_runtime.h>
#include <cuda_bf16.h>
#include <cstdint>

#define NODES 40000
#define EDGES 640000
#define DIN   128
#define HC    128
#define OC    64
#define NTILES 5000   // 128 edges per tile

typedef unsigned long long ull;

// single dynamic-shared declaration for the whole TU
extern __shared__ char dynsm[];

// ---------------- device scratch ------------------------------------------
__device__ float g_xm[(size_t)NODES * HC];
__device__ float g_xs[(size_t)NODES * OC];
__device__ float g_denom[(size_t)NODES * 2];
__device__ float g_agg[(size_t)NODES * HC];
__device__ float g_le_fallback[(size_t)EDGES * HC];
// W_edge^T interleaved bf16 hi/lo image: B2[n][ks][tig] = 4 contiguous words
// {hi(kw), hi(kw+4), lo(kw), lo(kw+4)}, kw = ks*8+tig. Row stride 132 words
// (528B, padded) -> one LDS.128 per MMA fragment pair, conflict-free.
__device__ __align__(16) uint32_t g_B2[128 * 132];

// ---------------- helpers ----------------------------------------------------
__device__ __forceinline__ void red_add_v2(float* p, float a, float b) {
    asm volatile("red.global.add.v2.f32 [%0], {%1,%2};"
                 :: "l"(p), "f"(a), "f"(b) : "memory");
}
__device__ __forceinline__ void red_add_f32(float* p, float v) {
    asm volatile("red.global.add.f32 [%0], %1;" :: "l"(p), "f"(v) : "memory");
}
// m16n8k16 row.col bf16 MMA, f32 accumulate (base-target HMMA)
__device__ __forceinline__ void mma_bf16(float* c, const uint32_t* a, const uint32_t* b) {
    asm volatile("mma.sync.aligned.m16n8k16.row.col.f32.bf16.bf16.f32 "
                 "{%0,%1,%2,%3}, {%4,%5,%6,%7}, {%8,%9}, {%0,%1,%2,%3};"
                 : "+f"(c[0]), "+f"(c[1]), "+f"(c[2]), "+f"(c[3])
                 : "r"(a[0]), "r"(a[1]), "r"(a[2]), "r"(a[3]), "r"(b[0]), "r"(b[1]));
}
__device__ __forceinline__ uint32_t pack_bf16x2_split(float v0, float v1, uint32_t& lo) {
    __nv_bfloat16 h0 = __float2bfloat16_rn(v0);
    __nv_bfloat16 h1 = __float2bfloat16_rn(v1);
    __nv_bfloat16 l0 = __float2bfloat16_rn(v0 - __bfloat162float(h0));
    __nv_bfloat16 l1 = __float2bfloat16_rn(v1 - __bfloat162float(h1));
    lo = (uint32_t)__bfloat16_as_ushort(l0) | ((uint32_t)__bfloat16_as_ushort(l1) << 16);
    return (uint32_t)__bfloat16_as_ushort(h0) | ((uint32_t)__bfloat16_as_ushort(h1) << 16);
}

// ---------------- K0: init --------------------------------------------------
__global__ void init_kernel() {
    int i = blockIdx.x * blockDim.x + threadIdx.x;
    if (i < NODES * HC) g_agg[i] = 0.0f;
    if (i < NODES * 2)  g_denom[i] = 0.0f;
}

// ---------------- prep: W_edge^T -> interleaved bf16 hi/lo image -------------
__global__ void prep_kernel(const float* __restrict__ W_edge) {
    int p = blockIdx.x * 256 + threadIdx.x;   // 8192 = 128 n x 64 k-pairs
    if (p >= 8192) return;
    int n  = p >> 6;
    int kp = p & 63;          // k-pair index: kw = kp (word of 2 bf16)
    int k  = kp * 2;
    int ks  = kp >> 3;        // 0..7
    int j   = kp & 7;         // 0..7
    int tig = j & 3;          // 0..3
    int sel = j >> 2;         // 0: kw slot, 1: kw+4 slot
    uint32_t lo;
    uint32_t hi = pack_bf16x2_split(W_edge[k * HC + n], W_edge[(k + 1) * HC + n], lo);
    int base = n * 132 + ks * 16 + tig * 4;
    g_B2[base + sel]     = hi;
    g_B2[base + 2 + sel] = lo;
}

// ---------------- K1: node GEMMs (known-good) --------------------------------
__global__ void node_kernel(const float* __restrict__ x,
                            const float* __restrict__ W_msg,
                            const float* __restrict__ b_msg,
                            const float* __restrict__ W_self,
                            const float* __restrict__ b_self) {
    float* smf = (float*)dynsm;
    float* Xs = smf;
    float* Wm = smf + 64 * 128;
    float* Wf = Wm + 128 * 128;
    int tid = threadIdx.x;

    const float4* xg = (const float4*)(x + (size_t)blockIdx.x * 64 * DIN);
#pragma unroll
    for (int i = 0; i < 8; i++)  ((float4*)Xs)[tid + i * 256] = xg[tid + i * 256];
#pragma unroll
    for (int i = 0; i < 16; i++) ((float4*)Wm)[tid + i * 256] = ((const float4*)W_msg)[tid + i * 256];
#pragma unroll
    for (int i = 0; i < 8; i++)  ((float4*)Wf)[tid + i * 256] = ((const float4*)W_self)[tid + i * 256];
    __syncthreads();

    int lane = tid & 31, ty = tid >> 5;
    int lane4 = lane * 4;
    const float* Xr = Xs + ty * 8 * DIN;
    {
        float acc[8][4];
#pragma unroll
        for (int r = 0; r < 8; r++) { acc[r][0] = acc[r][1] = acc[r][2] = acc[r][3] = 0.f; }
#pragma unroll 4
        for (int k = 0; k < 128; k++) {
            float4 bq = *(float4*)(Wm + k * 128 + lane4);
#pragma unroll
            for (int r = 0; r < 8; r++) {
                float av = Xr[r * DIN + k];
                acc[r][0] += av * bq.x; acc[r][1] += av * bq.y;
                acc[r][2] += av * bq.z; acc[r][3] += av * bq.w;
            }
        }
        float4 bm = *(const float4*)(b_msg + lane4);
#pragma unroll
        for (int r = 0; r < 8; r++) {
            int n = blockIdx.x * 64 + ty * 8 + r;
            float4 v; v.x = acc[r][0] + bm.x; v.y = acc[r][1] + bm.y;
            v.z = acc[r][2] + bm.z; v.w = acc[r][3] + bm.w;
            *(float4*)(g_xm + (size_t)n * HC + lane4) = v;
        }
    }
    {
        int lane2 = lane * 2;
        float acc[8][2];
#pragma unroll
        for (int r = 0; r < 8; r++) { acc[r][0] = acc[r][1] = 0.f; }
#pragma unroll 4
        for (int k = 0; k < 128; k++) {
            float2 bq = *(float2*)(Wf + k * 64 + lane2);
#pragma unroll
            for (int r = 0; r < 8; r++) {
                float av = Xr[r * DIN + k];
                acc[r][0] += av * bq.x; acc[r][1] += av * bq.y;
            }
        }
        float2 bs = *(const float2*)(b_self + lane2);
#pragma unroll
        for (int r = 0; r < 8; r++) {
            int n = blockIdx.x * 64 + ty * 8 + r;
            float2 v; v.x = acc[r][0] + bs.x; v.y = acc[r][1] + bs.y;
            *(float2*)(g_xs + (size_t)n * OC + lane2) = v;
        }
    }
}

// ---------------- K2: warp-autonomous HMMA edge GEMM + fused scatter ---------
// R10 structure (best so far) with ONE change: interleaved B2 layout so each
// MMA's B fragments come from a single LDS.128 (256 -> 64 B-load instructions
// per warp-tile; the LSU dispatch floor was the serializer).
// Persistent CTAs, 2/SM. Tile = 128 edges; warp = 32 rows x 64 cols as two
// stacked m16 tiles sharing B fragments. No __syncthreads in the tile loop.
// warp w: rows [(w>>1)*32,+32), cols [(w&1)*64,+64)  (col half == head)
// smem: 0: bias[128] | 512: att[128] | 1024: B2 (67584)  -> total 68608
#define SM_B2    1024
#define SM_TOTAL 68608

__global__ void __launch_bounds__(256, 2) edge_kernel(
        const float* __restrict__ edge_attr,
        const float* __restrict__ b_edge,
        const float* __restrict__ att,
        const int*   __restrict__ srcIdx,
        const int*   __restrict__ dstIdx,
        float* __restrict__ le_out) {
    char* sm = dynsm;
    int tid = threadIdx.x;
    int wid = tid >> 5;
    int lane = tid & 31;
    float* b_s   = (float*)(sm);
    float* att_s = (float*)(sm + 512);
    uint32_t* B2 = (uint32_t*)(sm + SM_B2);

    // ---- prologue (once per CTA) ----
    if (tid < 128) { b_s[tid] = b_edge[tid]; att_s[tid] = att[tid]; }
    {
        const uint4* bsrc = (const uint4*)g_B2;
        uint4* bdst = (uint4*)B2;
#pragma unroll
        for (int i = 0; i < 17; i++) {
            int idx = tid + i * 256;
            if (idx < 4224) bdst[idx] = bsrc[idx];
        }
    }
    __syncthreads();   // the only block sync

    int rowg = wid >> 1;          // 0..3 -> rows rowg*32..+32
    int colg = wid & 1;           // 0..1 -> cols colg*64..+64  (== head)
    int r   = lane >> 2;          // 0..7
    int tig = lane & 3;           // 0..3
    int r0  = rowg * 32 + r;      // lane covers rows r0, r0+8 (mt=0), r0+16, r0+24 (mt=1)

    for (int t = blockIdx.x; t < NTILES; t += gridDim.x) {
        // A tile base, float2 (k-pair) units: row stride = 64 pairs
        const float2* A = (const float2*)(edge_attr + (size_t)t * 128 * DIN);

        float acc[2][8][4];
#pragma unroll
        for (int mt = 0; mt < 2; mt++)
#pragma unroll
            for (int nf = 0; nf < 8; nf++)
#pragma unroll
                for (int q = 0; q < 4; q++) acc[mt][nf][q] = 0.f;

        // prefetch first ks raw A: 8 float2 (2 m-tiles x rows r,r+8 x kw,kw+4)
        float2 raw[2][4];
        {
            int kw = tig;
#pragma unroll
            for (int mt = 0; mt < 2; mt++) {
                int R = r0 + mt * 16;
                raw[mt][0] = A[R * 64 + kw];       raw[mt][1] = A[(R + 8) * 64 + kw];
                raw[mt][2] = A[R * 64 + kw + 4];   raw[mt][3] = A[(R + 8) * 64 + kw + 4];
            }
        }
#pragma unroll
        for (int ks = 0; ks < 8; ks++) {
            int kw = ks * 8 + tig;
            uint32_t ah[2][4], al[2][4];
#pragma unroll
            for (int mt = 0; mt < 2; mt++) {
                ah[mt][0] = pack_bf16x2_split(raw[mt][0].x, raw[mt][0].y, al[mt][0]);
                ah[mt][1] = pack_bf16x2_split(raw[mt][1].x, raw[mt][1].y, al[mt][1]);
                ah[mt][2] = pack_bf16x2_split(raw[mt][2].x, raw[mt][2].y, al[mt][2]);
                ah[mt][3] = pack_bf16x2_split(raw[mt][3].x, raw[mt][3].y, al[mt][3]);
            }
            if (ks < 7) {
                int kn = kw + 8;
#pragma unroll
                for (int mt = 0; mt < 2; mt++) {
                    int R = r0 + mt * 16;
                    raw[mt][0] = A[R * 64 + kn];       raw[mt][1] = A[(R + 8) * 64 + kn];
                    raw[mt][2] = A[R * 64 + kn + 4];   raw[mt][3] = A[(R + 8) * 64 + kn + 4];
                }
            }
#pragma unroll
            for (int nf = 0; nf < 8; nf++) {
                // one LDS.128 fetches {bh0, bh1, bl0, bl1}
                int nb = (colg * 64 + nf * 8 + r) * 132 + ks * 16 + tig * 4;
                uint4 bq = *(uint4*)(B2 + nb);
                uint32_t bh[2] = { bq.x, bq.y };
                uint32_t bl[2] = { bq.z, bq.w };
#pragma unroll
                for (int mt = 0; mt < 2; mt++) {
                    mma_bf16(acc[mt][nf], ah[mt], bh);
                    mma_bf16(acc[mt][nf], ah[mt], bl);
                    mma_bf16(acc[mt][nf], al[mt], bh);
                }
            }
        }

        // ---- epilogue straight from fragments (per m-tile) ----
#pragma unroll
        for (int mt = 0; mt < 2; mt++) {
            int e0 = t * 128 + r0 + mt * 16;
            int e1 = e0 + 8;
            int s0 = srcIdx[e0], s1 = srcIdx[e1];
            int d0 = dstIdx[e0], d1 = dstIdx[e1];

            float dot0 = 0.f, dot1 = 0.f;
#pragma unroll
            for (int nf = 0; nf < 8; nf++) {
                int col = colg * 64 + nf * 8 + tig * 2;
                float2 bb = *(float2*)(b_s + col);
                float2 le0; le0.x = acc[mt][nf][0] + bb.x; le0.y = acc[mt][nf][1] + bb.y;
                float2 le1; le1.x = acc[mt][nf][2] + bb.x; le1.y = acc[mt][nf][3] + bb.y;
                *(float2*)(le_out + (size_t)e0 * HC + col) = le0;
                *(float2*)(le_out + (size_t)e1 * HC + col) = le1;
                float2 xv0 = *(const float2*)(g_xm + (size_t)s0 * HC + col);
                float2 xv1 = *(const float2*)(g_xm + (size_t)s1 * HC + col);
                acc[mt][nf][0] = le0.x + xv0.x; acc[mt][nf][1] = le0.y + xv0.y;
                acc[mt][nf][2] = le1.x + xv1.x; acc[mt][nf][3] = le1.y + xv1.y;
                float2 at = *(float2*)(att_s + col);
                dot0 += acc[mt][nf][0] * at.x + acc[mt][nf][1] * at.y;
                dot1 += acc[mt][nf][2] * at.x + acc[mt][nf][3] * at.y;
            }
            dot0 += __shfl_xor_sync(0xffffffffu, dot0, 1);
            dot0 += __shfl_xor_sync(0xffffffffu, dot0, 2);
            dot1 += __shfl_xor_sync(0xffffffffu, dot1, 1);
            dot1 += __shfl_xor_sync(0xffffffffu, dot1, 2);
            float lr0 = dot0 > 0.f ? dot0 : 0.2f * dot0;
            float lr1 = dot1 > 0.f ? dot1 : 0.2f * dot1;
            float ex0 = __expf(lr0);
            float ex1 = __expf(lr1);
            if (tig == 0) {
                red_add_f32(&g_denom[d0 * 2 + colg], ex0);
                red_add_f32(&g_denom[d1 * 2 + colg], ex1);
            }
#pragma unroll
            for (int nf = 0; nf < 8; nf++) {
                int col = colg * 64 + nf * 8 + tig * 2;
                red_add_v2(g_agg + (size_t)d0 * HC + col, acc[mt][nf][0] * ex0, acc[mt][nf][1] * ex0);
                red_add_v2(g_agg + (size_t)d1 * HC + col, acc[mt][nf][2] * ex1, acc[mt][nf][3] * ex1);
            }
        }
    }
}

// ---------------- K3: finalize ----------------------------------------------
__global__ void finalize_kernel(float* __restrict__ out) {
    int i = blockIdx.x * blockDim.x + threadIdx.x;
    if (i >= NODES * OC) return;
    int n = i >> 6;
    int c = i & 63;
    float d0 = g_denom[n * 2 + 0] + 1e-16f;
    float d1 = g_denom[n * 2 + 1] + 1e-16f;
    float v = 0.5f * (g_agg[(size_t)n * HC + c] / d0 + g_agg[(size_t)n * HC + 64 + c] / d1);
    out[i] = v + g_xs[i];
}

// ---------------- launch ------------------------------------------------------
extern "C" void kernel_launch(void* const* d_in, const int* in_sizes, int n_in,
                              void* d_out, int out_size) {
    const float* x        = (const float*)d_in[0];
    const float* edge_attr= (const float*)d_in[1];
    const float* W_msg    = (const float*)d_in[2];
    const float* b_msg    = (const float*)d_in[3];
    const float* W_edge   = (const float*)d_in[4];
    const float* b_edge   = (const float*)d_in[5];
    const float* W_self   = (const float*)d_in[6];
    const float* b_self   = (const float*)d_in[7];
    const float* att      = (const float*)d_in[8];
    const int*   ei       = (const int*)d_in[9];
    const int* srcI = ei;
    const int* dstI = ei + EDGES;

    float* out = (float*)d_out;
    float* le_out;
    bool le_in_out = (out_size >= NODES * OC + (long long)EDGES * HC);
    if (le_in_out) {
        le_out = out + (size_t)NODES * OC;
    } else {
        void* p = nullptr;
        cudaGetSymbolAddress(&p, g_le_fallback);
        le_out = (float*)p;
    }

    cudaFuncSetAttribute(node_kernel, cudaFuncAttributeMaxDynamicSharedMemorySize, 131072);
    cudaFuncSetAttribute(edge_kernel, cudaFuncAttributeMaxDynamicSharedMemorySize, SM_TOTAL);

    init_kernel<<<(NODES * HC + 255) / 256, 256>>>();
    prep_kernel<<<32, 256>>>(W_edge);
    node_kernel<<<NODES / 64, 256, 131072>>>(x, W_msg, b_msg, W_self, b_self);
    edge_kernel<<<296, 256, SM_TOTAL>>>(edge_attr, b_edge, att, srcI, dstI, le_out);
    finalize_kernel<<<(NODES * OC + 255) / 256, 256>>>(out);
}